// round 15
// baseline (speedup 1.0000x reference)
#include <cuda_runtime.h>
#include <cuda_fp16.h>
#include <cstdint>

// ---------------------------------------------------------------------------
// Problem constants
// ---------------------------------------------------------------------------
#define N_TABLES 64
#define VOCAB    1024
#define D_EA     128
#define D_CONT   129
#define MAXDAY   3650
#define P129H    132          // half stride for pe129 rows: 264B, 8B-aligned
#define ILP      4            // nodes per warp
#define PE_CHUNKS 8           // day-parallel chunks in k_pe

// ---------------------------------------------------------------------------
// Scratch (device globals; no allocation allowed)
// ---------------------------------------------------------------------------
__device__ __align__(16) __half g_pe129h[MAXDAY * P129H];   // ~0.96 MB
__device__ __align__(16) __half g_pe128h[MAXDAY * D_EA];    // ~0.93 MB
// Precombined categ table: tab'[id][v][:] = categ_tables[id][v][:] + ea[id][:]
__device__ float4 g_tab2[N_TABLES * VOCAB * (D_EA / 4)];    // 33.5 MB

// ---------------------------------------------------------------------------
// PE table generation. Grid (129, PE_CHUNKS). Integer fixed-point range
// reduction (q = day*theta wraps mod 2^32 == exact mod 2*pi).
// ---------------------------------------------------------------------------
__global__ void k_pe() {
    __shared__ unsigned int s_theta;
    int pair = blockIdx.x;
    bool is129 = pair < 65;
    int j = is129 ? pair : pair - 65;

    if (threadIdx.x == 0) {
        int d = is129 ? D_CONT : D_EA;
        const double INV_TWO_PI = 0.15915494309189533576888376337251;
        double invdiv = pow(10000.0, -(double)(2 * j) / (double)d);
        double turns  = invdiv * INV_TWO_PI;
        double frac   = turns - floor(turns);
        unsigned long long q64 = (unsigned long long)(frac * 4294967296.0 + 0.5);
        s_theta = (unsigned int)q64;
    }
    __syncthreads();
    unsigned int theta = s_theta;

    const float SCALE = 1.46291807926715968e-09f;   // 2*pi / 2^32
    int stride = blockDim.x * PE_CHUNKS;
    for (int day = blockIdx.y * blockDim.x + threadIdx.x; day < MAXDAY;
         day += stride) {
        unsigned int q = (unsigned int)day * theta;
        float f = (float)(int)q * SCALE;
        float s, c;
        sincosf(f, &s, &c);
        if (is129) {
            if (j == 64) {
                g_pe129h[day * P129H + 128] = __float2half(s);  // k=128 even -> sin
            } else {
                *reinterpret_cast<__half2*>(&g_pe129h[day * P129H + 2 * j]) =
                    __floats2half2_rn(s, c);
            }
        } else {
            *reinterpret_cast<__half2*>(&g_pe128h[day * D_EA + 2 * j]) =
                __floats2half2_rn(s, c);
        }
    }
}

// ---------------------------------------------------------------------------
// Precombine: g_tab2[row][k4] = tab4[row][k4] + ea4[row / VOCAB][k4].
// 2.1M float4s; ea rows are L1/L2 hits. ~64MB of DRAM traffic, ~8us.
// ---------------------------------------------------------------------------
__global__ void k_pre(const float4* __restrict__ tab4,
                      const float4* __restrict__ ea4) {
    int t = blockIdx.x * blockDim.x + threadIdx.x;
    if (t >= N_TABLES * VOCAB * (D_EA / 4)) return;
    int k4  = t & 31;
    int id  = t >> 15;            // t / (VOCAB * 32)
    float4 a = __ldg(ea4 + id * 32 + k4);
    float4 b = __ldg(tab4 + t);
    float4 r;
    r.x = b.x + a.x; r.y = b.y + a.y; r.z = b.z + a.z; r.w = b.w + a.w;
    g_tab2[t] = r;
}

// ---------------------------------------------------------------------------
// Fused main kernel, FULL variant: requires n % ILP == 0 and 16B-aligned
// inputs. ILP=4 nodes per warp; vectorized index loads; categ branch reads
// the precombined table (no ea gather). launch_bounds(256,7), no smem;
// streaming stores keep gather tables L2-resident.
// ---------------------------------------------------------------------------
__global__ __launch_bounds__(256, 7)
void k_main_full(const int* __restrict__ cont_ids,
                 const float* __restrict__ cont_vals,
                 const int* __restrict__ cont_days,
                 const int* __restrict__ categ_ids,
                 const int* __restrict__ categ_voc,
                 const int* __restrict__ categ_days,
                 const float* __restrict__ ea,
                 float* __restrict__ out,
                 float4* __restrict__ out_categ4,
                 int n) {
    int gw   = (blockIdx.x * blockDim.x + threadIdx.x) >> 5;
    int lane = threadIdx.x & 31;
    int ngrp = n / ILP;

    if (gw < ngrp) {
        // ---------------- continuous branch ----------------
        int base = gw * ILP;

        int4 idv  = __ldg(reinterpret_cast<const int4*>(cont_ids)  + gw);
        int4 dayv = __ldg(reinterpret_cast<const int4*>(cont_days) + gw);
        int id[ILP]  = {idv.x,  idv.y,  idv.z,  idv.w};
        int day[ILP] = {dayv.x, dayv.y, dayv.z, dayv.w};

        // Front-batch the L2-latency PE reads.
        __half pv[ILP][4];
#pragma unroll
        for (int m = 0; m < ILP; m++) {
            const __half* perow = g_pe129h + day[m] * P129H;
#pragma unroll
            for (int j = 0; j < 4; j++)
                pv[m][j] = perow[lane + 32 * j];
        }
        float4 valv = __ldg(reinterpret_cast<const float4*>(cont_vals) + gw);
        float val[ILP] = {valv.x, valv.y, valv.z, valv.w};

        // ea rows are L1 hits; load inside the combine loop.
#pragma unroll
        for (int m = 0; m < ILP; m++) {
            const float* earow = ea + id[m] * D_EA;
            float* o = out + (base + m) * D_CONT;
#pragma unroll
            for (int j = 0; j < 4; j++) {
                int k = lane + 32 * j;
                __stcs(&o[k], __ldg(earow + k) + __half2float(pv[m][j]));
            }
            if (lane == 0)
                __stcs(&o[D_EA], val[m] +
                                 __half2float(g_pe129h[day[m] * P129H + D_EA]));
        }
    } else {
        // ---------------- categorical branch ----------------
        int g = gw - ngrp;
        if (g >= ngrp) return;
        int base = g * ILP;

        int4 idv  = __ldg(reinterpret_cast<const int4*>(categ_ids)  + g);
        int4 vv   = __ldg(reinterpret_cast<const int4*>(categ_voc)  + g);
        int4 dayv = __ldg(reinterpret_cast<const int4*>(categ_days) + g);
        int boff[ILP] = {(idv.x * VOCAB + vv.x) * 32 + lane,
                         (idv.y * VOCAB + vv.y) * 32 + lane,
                         (idv.z * VOCAB + vv.z) * 32 + lane,
                         (idv.w * VOCAB + vv.w) * 32 + lane};
        int poff[ILP] = {dayv.x * 32 + lane, dayv.y * 32 + lane,
                         dayv.z * 32 + lane, dayv.w * 32 + lane};

        // Front-batch the long-latency loads: precombined gather + PE rows.
        float4 b[ILP];
        uint2  p[ILP];
#pragma unroll
        for (int m = 0; m < ILP; m++) {
            b[m] = __ldg(g_tab2 + boff[m]);
            p[m] = *(reinterpret_cast<const uint2*>(g_pe128h) + poff[m]);
        }
#pragma unroll
        for (int m = 0; m < ILP; m++) {
            __half2 p01 = *reinterpret_cast<__half2*>(&p[m].x);
            __half2 p23 = *reinterpret_cast<__half2*>(&p[m].y);
            float2 f01 = __half22float2(p01);
            float2 f23 = __half22float2(p23);
            float4 r;
            r.x = b[m].x + f01.x;
            r.y = b[m].y + f01.y;
            r.z = b[m].z + f23.x;
            r.w = b[m].w + f23.y;
            __stcs(&out_categ4[(base + m) * 32 + lane], r);
        }
    }
}

// ---------------------------------------------------------------------------
// Generic fallback (tail-safe) — used only when n % ILP != 0 or inputs
// misaligned. Reads the ORIGINAL tables (no precombine dependency).
// ---------------------------------------------------------------------------
__global__ __launch_bounds__(256, 5)
void k_main(const int* __restrict__ cont_ids,
            const float* __restrict__ cont_vals,
            const int* __restrict__ cont_days,
            const int* __restrict__ categ_ids,
            const int* __restrict__ categ_voc,
            const int* __restrict__ categ_days,
            const float* __restrict__ ea,
            const float4* __restrict__ tab4,
            float* __restrict__ out,
            float4* __restrict__ out_categ4,
            int n) {
    int gw   = (blockIdx.x * blockDim.x + threadIdx.x) >> 5;
    int lane = threadIdx.x & 31;
    int ngrp = (n + ILP - 1) / ILP;

    if (gw < ngrp) {
        int base = gw * ILP;
        int cnt  = n - base; if (cnt > ILP) cnt = ILP;
        int id[ILP], day[ILP];
#pragma unroll
        for (int m = 0; m < ILP; m++) {
            int w = (m < cnt) ? base + m : base;
            id[m]  = __ldg(cont_ids  + w);
            day[m] = __ldg(cont_days + w);
        }
        __half pv[ILP][4];
#pragma unroll
        for (int m = 0; m < ILP; m++) {
            const __half* perow = g_pe129h + day[m] * P129H;
#pragma unroll
            for (int j = 0; j < 4; j++)
                pv[m][j] = perow[lane + 32 * j];
        }
#pragma unroll
        for (int m = 0; m < ILP; m++) {
            if (m >= cnt) break;
            const float* earow = ea + id[m] * D_EA;
            float* o = out + (base + m) * D_CONT;
#pragma unroll
            for (int j = 0; j < 4; j++) {
                int k = lane + 32 * j;
                o[k] = __ldg(earow + k) + __half2float(pv[m][j]);
            }
            if (lane == 0)
                o[D_EA] = __ldg(cont_vals + base + m) +
                          __half2float(g_pe129h[day[m] * P129H + D_EA]);
        }
    } else {
        int g = gw - ngrp;
        if (g >= ngrp) return;
        int base = g * ILP;
        int cnt  = n - base; if (cnt > ILP) cnt = ILP;
        int id[ILP], v[ILP], day[ILP];
#pragma unroll
        for (int m = 0; m < ILP; m++) {
            int w = (m < cnt) ? base + m : base;
            id[m]  = __ldg(categ_ids  + w);
            v[m]   = __ldg(categ_voc  + w);
            day[m] = __ldg(categ_days + w);
        }
        float4 b[ILP];
        uint2  p[ILP];
#pragma unroll
        for (int m = 0; m < ILP; m++) {
            b[m] = __ldg(tab4 + (id[m] * VOCAB + v[m]) * 32 + lane);
            p[m] = *(reinterpret_cast<const uint2*>(g_pe128h) + day[m] * 32 + lane);
        }
        const float4* ea4 = reinterpret_cast<const float4*>(ea);
#pragma unroll
        for (int m = 0; m < ILP; m++) {
            if (m >= cnt) break;
            float4 a = __ldg(ea4 + id[m] * 32 + lane);
            __half2 p01 = *reinterpret_cast<__half2*>(&p[m].x);
            __half2 p23 = *reinterpret_cast<__half2*>(&p[m].y);
            float2 f01 = __half22float2(p01);
            float2 f23 = __half22float2(p23);
            float4 r;
            r.x = a.x + b[m].x + f01.x;
            r.y = a.y + b[m].y + f01.y;
            r.z = a.z + b[m].z + f23.x;
            r.w = a.w + b[m].w + f23.y;
            out_categ4[(base + m) * 32 + lane] = r;
        }
    }
}

// ---------------------------------------------------------------------------
// Scalar fallback kernels (used only if categ output offset is misaligned).
// ---------------------------------------------------------------------------
__global__ void k_cont(const int* __restrict__ ids,
                       const float* __restrict__ vals,
                       const int* __restrict__ days,
                       const float* __restrict__ ea,
                       float* __restrict__ out, int n) {
    int w    = (blockIdx.x * blockDim.x + threadIdx.x) >> 5;
    int lane = threadIdx.x & 31;
    if (w >= n) return;
    int id  = __ldg(ids  + w);
    int day = __ldg(days + w);
    const float*  earow = ea + id * D_EA;
    const __half* perow = g_pe129h + day * P129H;
    float* o = out + (long long)w * D_CONT;
#pragma unroll
    for (int j = 0; j < 4; j++) {
        int k = lane + 32 * j;
        o[k] = __ldg(earow + k) + __half2float(perow[k]);
    }
    if (lane == 0) o[D_EA] = __ldg(vals + w) + __half2float(perow[D_EA]);
}

__global__ void k_categ_scalar(const int* __restrict__ ids,
                               const int* __restrict__ vocab,
                               const int* __restrict__ days,
                               const float* __restrict__ ea,
                               const float* __restrict__ tab,
                               float* __restrict__ out, int n) {
    int w    = (blockIdx.x * blockDim.x + threadIdx.x) >> 5;
    int lane = threadIdx.x & 31;
    if (w >= n) return;
    int id  = __ldg(ids   + w);
    int v   = __ldg(vocab + w);
    int day = __ldg(days  + w);
    const float*  earow = ea + id * D_EA;
    const float*  trow  = tab + ((long long)id * VOCAB + v) * D_EA;
    const __half* perow = g_pe128h + day * D_EA;
    float* o = out + (long long)w * D_EA;
#pragma unroll
    for (int j = 0; j < 4; j++) {
        int k = lane + 32 * j;
        o[k] = __ldg(earow + k) + __ldg(trow + k) + __half2float(perow[k]);
    }
}

// ---------------------------------------------------------------------------
// Launch
// ---------------------------------------------------------------------------
extern "C" void kernel_launch(void* const* d_in, const int* in_sizes, int n_in,
                              void* d_out, int out_size) {
    const int*   cont_ids   = (const int*)  d_in[0];
    const float* cont_vals  = (const float*)d_in[1];
    const int*   cont_days  = (const int*)  d_in[2];
    const int*   categ_ids  = (const int*)  d_in[3];
    const int*   categ_voc  = (const int*)  d_in[4];
    const int*   categ_days = (const int*)  d_in[5];
    const float* ea_table   = (const float*)d_in[6];
    const float* categ_tab  = (const float*)d_in[7];

    const int n = in_sizes[0];

    float* out       = (float*)d_out;
    float* out_categ = out + (long long)n * D_CONT;

    // PE tables (fp16): 129 x PE_CHUNKS blocks, ~2 sincosf iters per thread.
    {
        dim3 grid(129, PE_CHUNKS);
        k_pe<<<grid, 256>>>();
    }

    bool in_aligned =
        ((((unsigned long long)(size_t)cont_ids)   & 15ULL) == 0ULL) &&
        ((((unsigned long long)(size_t)cont_vals)  & 15ULL) == 0ULL) &&
        ((((unsigned long long)(size_t)cont_days)  & 15ULL) == 0ULL) &&
        ((((unsigned long long)(size_t)categ_ids)  & 15ULL) == 0ULL) &&
        ((((unsigned long long)(size_t)categ_voc)  & 15ULL) == 0ULL) &&
        ((((unsigned long long)(size_t)categ_days) & 15ULL) == 0ULL) &&
        ((((unsigned long long)(size_t)ea_table)   & 15ULL) == 0ULL) &&
        ((((unsigned long long)(size_t)categ_tab)  & 15ULL) == 0ULL);
    bool aligned = ((((long long)n * D_CONT) & 3) == 0) &&
                   ((((unsigned long long)(size_t)out_categ) & 15ULL) == 0ULL);

    if (aligned && in_aligned && (n % ILP) == 0) {
        // Precombine categ table (+ea) into device scratch; leaves it hot in L2.
        {
            int total = N_TABLES * VOCAB * (D_EA / 4);
            k_pre<<<(total + 255) / 256, 256>>>((const float4*)categ_tab,
                                                (const float4*)ea_table);
        }
        long long ngrp  = n / ILP;
        long long warps = 2LL * ngrp;
        int blocks = (int)((warps + 7) / 8);
        k_main_full<<<blocks, 256>>>(cont_ids, cont_vals, cont_days,
                                     categ_ids, categ_voc, categ_days,
                                     ea_table, out, (float4*)out_categ, n);
    } else if (aligned) {
        long long ngrp  = (n + ILP - 1) / ILP;
        long long warps = 2LL * ngrp;
        int blocks = (int)((warps + 7) / 8);
        k_main<<<blocks, 256>>>(cont_ids, cont_vals, cont_days,
                                categ_ids, categ_voc, categ_days,
                                ea_table, (const float4*)categ_tab,
                                out, (float4*)out_categ, n);
    } else {
        int blocks = (n + 7) / 8;
        k_cont<<<blocks, 256>>>(cont_ids, cont_vals, cont_days, ea_table, out, n);
        k_categ_scalar<<<blocks, 256>>>(categ_ids, categ_voc, categ_days,
                                        ea_table, categ_tab, out_categ, n);
    }
}

// round 16
// speedup vs baseline: 1.0348x; 1.0348x over previous
#include <cuda_runtime.h>
#include <cuda_fp16.h>
#include <cstdint>

// ---------------------------------------------------------------------------
// Problem constants
// ---------------------------------------------------------------------------
#define N_TABLES 64
#define VOCAB    1024
#define D_EA     128
#define D_CONT   129
#define MAXDAY   3650
#define P129H    132          // half stride for pe129 rows: 264B, 8B-aligned
#define ILP      4            // nodes per warp
#define PE_CHUNKS 8           // day-parallel chunks in k_pe

// ---------------------------------------------------------------------------
// Scratch (device globals; no allocation allowed)
// ---------------------------------------------------------------------------
__device__ __align__(16) __half g_pe129h[MAXDAY * P129H];   // ~0.96 MB
__device__ __align__(16) __half g_pe128h[MAXDAY * D_EA];    // ~0.93 MB

// ---------------------------------------------------------------------------
// PE table generation. Grid (129, PE_CHUNKS). Integer fixed-point range
// reduction (q = day*theta wraps mod 2^32 == exact mod 2*pi) delivers
// |f| <= pi, so the MUFU fast path __sincosf (abs err ~4e-7 on [-pi,pi])
// is exact relative to the fp16 quantization (2.4e-4) of the tables.
// ---------------------------------------------------------------------------
__global__ void k_pe() {
    __shared__ unsigned int s_theta;
    int pair = blockIdx.x;
    bool is129 = pair < 65;
    int j = is129 ? pair : pair - 65;

    if (threadIdx.x == 0) {
        int d = is129 ? D_CONT : D_EA;
        const double INV_TWO_PI = 0.15915494309189533576888376337251;
        double invdiv = pow(10000.0, -(double)(2 * j) / (double)d);
        double turns  = invdiv * INV_TWO_PI;
        double frac   = turns - floor(turns);
        unsigned long long q64 = (unsigned long long)(frac * 4294967296.0 + 0.5);
        s_theta = (unsigned int)q64;
    }
    __syncthreads();
    unsigned int theta = s_theta;

    const float SCALE = 1.46291807926715968e-09f;   // 2*pi / 2^32
    int stride = blockDim.x * PE_CHUNKS;
    for (int day = blockIdx.y * blockDim.x + threadIdx.x; day < MAXDAY;
         day += stride) {
        unsigned int q = (unsigned int)day * theta;
        float f = (float)(int)q * SCALE;
        float s, c;
        __sincosf(f, &s, &c);          // MUFU fast path; |f| <= pi guaranteed
        if (is129) {
            if (j == 64) {
                g_pe129h[day * P129H + 128] = __float2half(s);  // k=128 even -> sin
            } else {
                *reinterpret_cast<__half2*>(&g_pe129h[day * P129H + 2 * j]) =
                    __floats2half2_rn(s, c);
            }
        } else {
            *reinterpret_cast<__half2*>(&g_pe128h[day * D_EA + 2 * j]) =
                __floats2half2_rn(s, c);
        }
    }
}

// ---------------------------------------------------------------------------
// Fused main kernel, FULL variant (R14 measured-best config, restored):
// requires n % ILP == 0 and 16B-aligned input arrays. ILP=4 nodes per warp;
// per-node scalars (ids/voc/days/vals) fetched as single int4/float4 loads.
// Long-latency loads front-batched; ea rows (L1-resident 32KB) loaded in
// the combine loop. launch_bounds(256,7), no smem; streaming stores.
// ---------------------------------------------------------------------------
__global__ __launch_bounds__(256, 7)
void k_main_full(const int* __restrict__ cont_ids,
                 const float* __restrict__ cont_vals,
                 const int* __restrict__ cont_days,
                 const int* __restrict__ categ_ids,
                 const int* __restrict__ categ_voc,
                 const int* __restrict__ categ_days,
                 const float* __restrict__ ea,
                 const float4* __restrict__ tab4,
                 float* __restrict__ out,
                 float4* __restrict__ out_categ4,
                 int n) {
    int gw   = (blockIdx.x * blockDim.x + threadIdx.x) >> 5;
    int lane = threadIdx.x & 31;
    int ngrp = n / ILP;

    if (gw < ngrp) {
        // ---------------- continuous branch ----------------
        int base = gw * ILP;

        int4 idv  = __ldg(reinterpret_cast<const int4*>(cont_ids)  + gw);
        int4 dayv = __ldg(reinterpret_cast<const int4*>(cont_days) + gw);
        int id[ILP]  = {idv.x,  idv.y,  idv.z,  idv.w};
        int day[ILP] = {dayv.x, dayv.y, dayv.z, dayv.w};

        // Front-batch the L2-latency PE reads.
        __half pv[ILP][4];
#pragma unroll
        for (int m = 0; m < ILP; m++) {
            const __half* perow = g_pe129h + day[m] * P129H;
#pragma unroll
            for (int j = 0; j < 4; j++)
                pv[m][j] = perow[lane + 32 * j];
        }
        float4 valv = __ldg(reinterpret_cast<const float4*>(cont_vals) + gw);
        float val[ILP] = {valv.x, valv.y, valv.z, valv.w};

        // ea rows are L1 hits; load inside the combine loop.
#pragma unroll
        for (int m = 0; m < ILP; m++) {
            const float* earow = ea + id[m] * D_EA;
            float* o = out + (base + m) * D_CONT;
#pragma unroll
            for (int j = 0; j < 4; j++) {
                int k = lane + 32 * j;
                __stcs(&o[k], __ldg(earow + k) + __half2float(pv[m][j]));
            }
            if (lane == 0)
                __stcs(&o[D_EA], val[m] +
                                 __half2float(g_pe129h[day[m] * P129H + D_EA]));
        }
    } else {
        // ---------------- categorical branch ----------------
        int g = gw - ngrp;
        if (g >= ngrp) return;
        int base = g * ILP;

        int4 idv  = __ldg(reinterpret_cast<const int4*>(categ_ids)  + g);
        int4 vv   = __ldg(reinterpret_cast<const int4*>(categ_voc)  + g);
        int4 dayv = __ldg(reinterpret_cast<const int4*>(categ_days) + g);
        int id[ILP] = {idv.x, idv.y, idv.z, idv.w};
        int boff[ILP] = {(idv.x * VOCAB + vv.x) * 32 + lane,
                         (idv.y * VOCAB + vv.y) * 32 + lane,
                         (idv.z * VOCAB + vv.z) * 32 + lane,
                         (idv.w * VOCAB + vv.w) * 32 + lane};
        int poff[ILP] = {dayv.x * 32 + lane, dayv.y * 32 + lane,
                         dayv.z * 32 + lane, dayv.w * 32 + lane};

        // Front-batch the long-latency loads: table gather + PE rows.
        float4 b[ILP];
        uint2  p[ILP];
#pragma unroll
        for (int m = 0; m < ILP; m++) {
            b[m] = __ldg(tab4 + boff[m]);
            p[m] = *(reinterpret_cast<const uint2*>(g_pe128h) + poff[m]);
        }
        // ea rows are L1 hits; load inside the combine loop.
        const float4* ea4 = reinterpret_cast<const float4*>(ea);
#pragma unroll
        for (int m = 0; m < ILP; m++) {
            float4 a = __ldg(ea4 + id[m] * 32 + lane);
            __half2 p01 = *reinterpret_cast<__half2*>(&p[m].x);
            __half2 p23 = *reinterpret_cast<__half2*>(&p[m].y);
            float2 f01 = __half22float2(p01);
            float2 f23 = __half22float2(p23);
            float4 r;
            r.x = a.x + b[m].x + f01.x;
            r.y = a.y + b[m].y + f01.y;
            r.z = a.z + b[m].z + f23.x;
            r.w = a.w + b[m].w + f23.y;
            __stcs(&out_categ4[(base + m) * 32 + lane], r);
        }
    }
}

// ---------------------------------------------------------------------------
// Generic fallback (tail-safe) — used only when n % ILP != 0.
// ---------------------------------------------------------------------------
__global__ __launch_bounds__(256, 5)
void k_main(const int* __restrict__ cont_ids,
            const float* __restrict__ cont_vals,
            const int* __restrict__ cont_days,
            const int* __restrict__ categ_ids,
            const int* __restrict__ categ_voc,
            const int* __restrict__ categ_days,
            const float* __restrict__ ea,
            const float4* __restrict__ tab4,
            float* __restrict__ out,
            float4* __restrict__ out_categ4,
            int n) {
    int gw   = (blockIdx.x * blockDim.x + threadIdx.x) >> 5;
    int lane = threadIdx.x & 31;
    int ngrp = (n + ILP - 1) / ILP;

    if (gw < ngrp) {
        int base = gw * ILP;
        int cnt  = n - base; if (cnt > ILP) cnt = ILP;
        int id[ILP], day[ILP];
#pragma unroll
        for (int m = 0; m < ILP; m++) {
            int w = (m < cnt) ? base + m : base;
            id[m]  = __ldg(cont_ids  + w);
            day[m] = __ldg(cont_days + w);
        }
        __half pv[ILP][4];
#pragma unroll
        for (int m = 0; m < ILP; m++) {
            const __half* perow = g_pe129h + day[m] * P129H;
#pragma unroll
            for (int j = 0; j < 4; j++)
                pv[m][j] = perow[lane + 32 * j];
        }
#pragma unroll
        for (int m = 0; m < ILP; m++) {
            if (m >= cnt) break;
            const float* earow = ea + id[m] * D_EA;
            float* o = out + (base + m) * D_CONT;
#pragma unroll
            for (int j = 0; j < 4; j++) {
                int k = lane + 32 * j;
                o[k] = __ldg(earow + k) + __half2float(pv[m][j]);
            }
            if (lane == 0)
                o[D_EA] = __ldg(cont_vals + base + m) +
                          __half2float(g_pe129h[day[m] * P129H + D_EA]);
        }
    } else {
        int g = gw - ngrp;
        if (g >= ngrp) return;
        int base = g * ILP;
        int cnt  = n - base; if (cnt > ILP) cnt = ILP;
        int id[ILP], v[ILP], day[ILP];
#pragma unroll
        for (int m = 0; m < ILP; m++) {
            int w = (m < cnt) ? base + m : base;
            id[m]  = __ldg(categ_ids  + w);
            v[m]   = __ldg(categ_voc  + w);
            day[m] = __ldg(categ_days + w);
        }
        float4 b[ILP];
        uint2  p[ILP];
#pragma unroll
        for (int m = 0; m < ILP; m++) {
            b[m] = __ldg(tab4 + (id[m] * VOCAB + v[m]) * 32 + lane);
            p[m] = *(reinterpret_cast<const uint2*>(g_pe128h) + day[m] * 32 + lane);
        }
        const float4* ea4 = reinterpret_cast<const float4*>(ea);
#pragma unroll
        for (int m = 0; m < ILP; m++) {
            if (m >= cnt) break;
            float4 a = __ldg(ea4 + id[m] * 32 + lane);
            __half2 p01 = *reinterpret_cast<__half2*>(&p[m].x);
            __half2 p23 = *reinterpret_cast<__half2*>(&p[m].y);
            float2 f01 = __half22float2(p01);
            float2 f23 = __half22float2(p23);
            float4 r;
            r.x = a.x + b[m].x + f01.x;
            r.y = a.y + b[m].y + f01.y;
            r.z = a.z + b[m].z + f23.x;
            r.w = a.w + b[m].w + f23.y;
            out_categ4[(base + m) * 32 + lane] = r;
        }
    }
}

// ---------------------------------------------------------------------------
// Scalar fallback kernels (used only if categ output offset is misaligned).
// ---------------------------------------------------------------------------
__global__ void k_cont(const int* __restrict__ ids,
                       const float* __restrict__ vals,
                       const int* __restrict__ days,
                       const float* __restrict__ ea,
                       float* __restrict__ out, int n) {
    int w    = (blockIdx.x * blockDim.x + threadIdx.x) >> 5;
    int lane = threadIdx.x & 31;
    if (w >= n) return;
    int id  = __ldg(ids  + w);
    int day = __ldg(days + w);
    const float*  earow = ea + id * D_EA;
    const __half* perow = g_pe129h + day * P129H;
    float* o = out + (long long)w * D_CONT;
#pragma unroll
    for (int j = 0; j < 4; j++) {
        int k = lane + 32 * j;
        o[k] = __ldg(earow + k) + __half2float(perow[k]);
    }
    if (lane == 0) o[D_EA] = __ldg(vals + w) + __half2float(perow[D_EA]);
}

__global__ void k_categ_scalar(const int* __restrict__ ids,
                               const int* __restrict__ vocab,
                               const int* __restrict__ days,
                               const float* __restrict__ ea,
                               const float* __restrict__ tab,
                               float* __restrict__ out, int n) {
    int w    = (blockIdx.x * blockDim.x + threadIdx.x) >> 5;
    int lane = threadIdx.x & 31;
    if (w >= n) return;
    int id  = __ldg(ids   + w);
    int v   = __ldg(vocab + w);
    int day = __ldg(days  + w);
    const float*  earow = ea + id * D_EA;
    const float*  trow  = tab + ((long long)id * VOCAB + v) * D_EA;
    const __half* perow = g_pe128h + day * D_EA;
    float* o = out + (long long)w * D_EA;
#pragma unroll
    for (int j = 0; j < 4; j++) {
        int k = lane + 32 * j;
        o[k] = __ldg(earow + k) + __ldg(trow + k) + __half2float(perow[k]);
    }
}

// ---------------------------------------------------------------------------
// Launch
// ---------------------------------------------------------------------------
extern "C" void kernel_launch(void* const* d_in, const int* in_sizes, int n_in,
                              void* d_out, int out_size) {
    const int*   cont_ids   = (const int*)  d_in[0];
    const float* cont_vals  = (const float*)d_in[1];
    const int*   cont_days  = (const int*)  d_in[2];
    const int*   categ_ids  = (const int*)  d_in[3];
    const int*   categ_voc  = (const int*)  d_in[4];
    const int*   categ_days = (const int*)  d_in[5];
    const float* ea_table   = (const float*)d_in[6];
    const float* categ_tab  = (const float*)d_in[7];

    const int n = in_sizes[0];

    float* out       = (float*)d_out;
    float* out_categ = out + (long long)n * D_CONT;

    // PE tables (fp16): 129 x PE_CHUNKS blocks, ~2 sincos iters per thread.
    {
        dim3 grid(129, PE_CHUNKS);
        k_pe<<<grid, 256>>>();
    }

    // Vectorized-index full variant also needs 16B-aligned input arrays.
    bool in_aligned =
        ((((unsigned long long)(size_t)cont_ids)   & 15ULL) == 0ULL) &&
        ((((unsigned long long)(size_t)cont_vals)  & 15ULL) == 0ULL) &&
        ((((unsigned long long)(size_t)cont_days)  & 15ULL) == 0ULL) &&
        ((((unsigned long long)(size_t)categ_ids)  & 15ULL) == 0ULL) &&
        ((((unsigned long long)(size_t)categ_voc)  & 15ULL) == 0ULL) &&
        ((((unsigned long long)(size_t)categ_days) & 15ULL) == 0ULL);
    bool aligned = ((((long long)n * D_CONT) & 3) == 0) &&
                   ((((unsigned long long)(size_t)out_categ) & 15ULL) == 0ULL);
    if (aligned && in_aligned && (n % ILP) == 0) {
        long long ngrp  = n / ILP;
        long long warps = 2LL * ngrp;
        int blocks = (int)((warps + 7) / 8);
        k_main_full<<<blocks, 256>>>(cont_ids, cont_vals, cont_days,
                                     categ_ids, categ_voc, categ_days,
                                     ea_table, (const float4*)categ_tab,
                                     out, (float4*)out_categ, n);
    } else if (aligned) {
        long long ngrp  = (n + ILP - 1) / ILP;
        long long warps = 2LL * ngrp;
        int blocks = (int)((warps + 7) / 8);
        k_main<<<blocks, 256>>>(cont_ids, cont_vals, cont_days,
                                categ_ids, categ_voc, categ_days,
                                ea_table, (const float4*)categ_tab,
                                out, (float4*)out_categ, n);
    } else {
        int blocks = (n + 7) / 8;
        k_cont<<<blocks, 256>>>(cont_ids, cont_vals, cont_days, ea_table, out, n);
        k_categ_scalar<<<blocks, 256>>>(categ_ids, categ_voc, categ_days,
                                        ea_table, categ_tab, out_categ, n);
    }
}